// round 2
// baseline (speedup 1.0000x reference)
#include <cuda_runtime.h>
#include <cuda_bf16.h>
#include <math.h>
#include <float.h>

// Problem constants (fixed by the dataset)
#define PB   64      // batch
#define PH   32      // query heads
#define PKVH 8       // kv heads
#define PD   128     // head dim
#define PBS  128     // kv block size
#define PBLK_PER_SEQ 16
#define PNB  (PB * PBLK_PER_SEQ)   // 1024 blocks in use
#define PG   (PH / PKVH)           // 4 (GQA group)
#define PSCALE 0.08838834764831845f  // 1/sqrt(128)

// ---------------- scratch (allocation-free: __device__ globals) ----------------
__device__ float g_m  [PNB * PKVH * PG];             // per-block max
__device__ float g_l  [PNB * PKVH * PG];             // per-block expsum
__device__ float g_out[(size_t)PNB * PKVH * PG * PD]; // unnormalized partial out (16 MB)

// ---------------- kernel 0: append new token's K/V into caches ----------------
// Idempotent (same values every replay) -> graph-safe & deterministic.
__global__ void scatter_kv_kernel(const float* __restrict__ k_new,
                                  const float* __restrict__ v_new,
                                  float* __restrict__ key_cache,
                                  float* __restrict__ value_cache,
                                  const int* __restrict__ block_indices,
                                  const int* __restrict__ block_offsets)
{
    int b = blockIdx.x;
    size_t dst = ((size_t)block_indices[b] * PBS + block_offsets[b]) * (PKVH * PD);
    size_t src = (size_t)b * (PKVH * PD);
    for (int i = threadIdx.x; i < PKVH * PD; i += blockDim.x) {
        key_cache  [dst + i] = k_new[src + i];
        value_cache[dst + i] = v_new[src + i];
    }
}

// ---------------- kernel 1: per-(block, kvh) partial attention ----------------
// 128 threads: lane l owns float4 d-slice [4l, 4l+4); warp w owns slots [32w, 32w+32).
__global__ __launch_bounds__(128) void attn_block_kernel(
    const float* __restrict__ query,
    const float* __restrict__ key_cache,
    const float* __restrict__ value_cache,
    const int*   __restrict__ block_list,
    const int*   __restrict__ block_groups,
    const float* __restrict__ block_bias)
{
    const int n   = blockIdx.x;
    const int kvh = blockIdx.y;
    const int t = threadIdx.x;
    const int w = t >> 5;
    const int l = t & 31;

    __shared__ float s_scores[PG][PBS];    // scores, then p=exp(score-max)
    __shared__ float s_bias[PBS];
    __shared__ float s_po[4][PG][PD];      // per-warp PV partials (8 KB)

    const int b   = block_groups[n];
    const int blk = block_list[n];

    s_bias[t] = block_bias[(size_t)n * PBS + t];

    // q fragment: q4[g] = SCALE * query[b, kvh*G+g, 4l..4l+3]
    float4 q4[PG];
    const float* qbase = query + (((size_t)b * PH + kvh * PG) * PD) + 4 * l;
#pragma unroll
    for (int g = 0; g < PG; g++) {
        float4 v = *(const float4*)(qbase + (size_t)g * PD);
        q4[g] = make_float4(v.x * PSCALE, v.y * PSCALE, v.z * PSCALE, v.w * PSCALE);
    }

    const size_t slot_stride = (size_t)PKVH * PD;
    const float* kbase = key_cache   + ((size_t)blk * PBS * PKVH + kvh) * PD + 4 * l;
    const float* vbase = value_cache + ((size_t)blk * PBS * PKVH + kvh) * PD + 4 * l;

    // ---- QK^T: each warp does 32 slots, dot over D via lane-split + shuffle reduce
#pragma unroll 4
    for (int i = 0; i < 32; i++) {
        int s = w * 32 + i;
        float4 k4 = *(const float4*)(kbase + (size_t)s * slot_stride);
        float p0 = q4[0].x * k4.x + q4[0].y * k4.y + q4[0].z * k4.z + q4[0].w * k4.w;
        float p1 = q4[1].x * k4.x + q4[1].y * k4.y + q4[1].z * k4.z + q4[1].w * k4.w;
        float p2 = q4[2].x * k4.x + q4[2].y * k4.y + q4[2].z * k4.z + q4[2].w * k4.w;
        float p3 = q4[3].x * k4.x + q4[3].y * k4.y + q4[3].z * k4.z + q4[3].w * k4.w;
#pragma unroll
        for (int off = 16; off > 0; off >>= 1) {
            p0 += __shfl_xor_sync(0xffffffffu, p0, off);
            p1 += __shfl_xor_sync(0xffffffffu, p1, off);
            p2 += __shfl_xor_sync(0xffffffffu, p2, off);
            p3 += __shfl_xor_sync(0xffffffffu, p3, off);
        }
        if (l == 0) {
            s_scores[0][s] = p0;
            s_scores[1][s] = p1;
            s_scores[2][s] = p2;
            s_scores[3][s] = p3;
        }
    }
    __syncthreads();

    // ---- per-block softmax: warp w handles g=w (G==4 warps)
    {
        const int g = w;
        float x0 = s_scores[g][l     ] + s_bias[l     ];
        float x1 = s_scores[g][l + 32] + s_bias[l + 32];
        float x2 = s_scores[g][l + 64] + s_bias[l + 64];
        float x3 = s_scores[g][l + 96] + s_bias[l + 96];
        float m = fmaxf(fmaxf(x0, x1), fmaxf(x2, x3));
#pragma unroll
        for (int off = 16; off > 0; off >>= 1)
            m = fmaxf(m, __shfl_xor_sync(0xffffffffu, m, off));
        float e0 = expf(x0 - m), e1 = expf(x1 - m);
        float e2 = expf(x2 - m), e3 = expf(x3 - m);
        float sum = e0 + e1 + e2 + e3;
#pragma unroll
        for (int off = 16; off > 0; off >>= 1)
            sum += __shfl_xor_sync(0xffffffffu, sum, off);
        s_scores[g][l     ] = e0;
        s_scores[g][l + 32] = e1;
        s_scores[g][l + 64] = e2;
        s_scores[g][l + 96] = e3;
        if (l == 0) {
            size_t idx = ((size_t)n * PKVH + kvh) * PG + g;
            g_m[idx] = m;
            g_l[idx] = sum;
        }
    }
    __syncthreads();

    // ---- P·V: warp w accumulates its 32 slots into float4 accumulators
    float4 o[PG];
#pragma unroll
    for (int g = 0; g < PG; g++) o[g] = make_float4(0.f, 0.f, 0.f, 0.f);

#pragma unroll 4
    for (int i = 0; i < 32; i++) {
        int s = w * 32 + i;
        float4 v4 = *(const float4*)(vbase + (size_t)s * slot_stride);
#pragma unroll
        for (int g = 0; g < PG; g++) {
            float p = s_scores[g][s];
            o[g].x += p * v4.x;
            o[g].y += p * v4.y;
            o[g].z += p * v4.z;
            o[g].w += p * v4.w;
        }
    }
#pragma unroll
    for (int g = 0; g < PG; g++)
        *(float4*)(&s_po[w][g][4 * l]) = o[g];
    __syncthreads();

    // cross-warp reduce + write unnormalized partial out
    {
        size_t base = (((size_t)n * PKVH + kvh) * PG) * PD;
#pragma unroll
        for (int g = 0; g < PG; g++) {
            float r = s_po[0][g][t] + s_po[1][g][t] + s_po[2][g][t] + s_po[3][g][t];
            g_out[base + (size_t)g * PD + t] = r;
        }
    }
}

// ---------------- kernel 2: cross-block combine per (b, kvh) ----------------
__global__ __launch_bounds__(128) void combine_kernel(
    const int* __restrict__ block_groups,
    float* __restrict__ out)
{
    const int b   = blockIdx.x;
    const int kvh = blockIdx.y;
    const int t = threadIdx.x;
    const int w = t >> 5;
    const int l = t & 31;

    __shared__ int   s_bg[PNB];
    __shared__ float s_M[PG], s_invL[PG];

    for (int i = t; i < PNB; i += 128) s_bg[i] = block_groups[i];
    __syncthreads();

    // warp w computes M, L for g=w
    {
        const int g = w;
        float M = -FLT_MAX;
        for (int n = l; n < PNB; n += 32)
            if (s_bg[n] == b)
                M = fmaxf(M, g_m[((size_t)n * PKVH + kvh) * PG + g]);
#pragma unroll
        for (int off = 16; off > 0; off >>= 1)
            M = fmaxf(M, __shfl_xor_sync(0xffffffffu, M, off));
        float L = 0.f;
        for (int n = l; n < PNB; n += 32)
            if (s_bg[n] == b) {
                size_t idx = ((size_t)n * PKVH + kvh) * PG + g;
                L += g_l[idx] * expf(g_m[idx] - M);
            }
#pragma unroll
        for (int off = 16; off > 0; off >>= 1)
            L += __shfl_xor_sync(0xffffffffu, L, off);
        if (l == 0) {
            s_M[g] = M;
            s_invL[g] = 1.0f / fmaxf(L, 1.17549435e-38f);
        }
    }
    __syncthreads();

    float acc[PG] = {0.f, 0.f, 0.f, 0.f};
    for (int n = 0; n < PNB; n++) {
        if (s_bg[n] != b) continue;
        size_t sbase = ((size_t)n * PKVH + kvh) * PG;
#pragma unroll
        for (int g = 0; g < PG; g++) {
            float c = expf(g_m[sbase + g] - s_M[g]) * s_invL[g];
            acc[g] += c * g_out[(sbase + g) * PD + t];
        }
    }

    size_t obase = ((size_t)b * PH + kvh * PG) * PD + t;
#pragma unroll
    for (int g = 0; g < PG; g++)
        out[obase + (size_t)g * PD] = acc[g];
}

// ---------------- launch ----------------
extern "C" void kernel_launch(void* const* d_in, const int* in_sizes, int n_in,
                              void* d_out, int out_size)
{
    const float* query        = (const float*)d_in[0];
    const float* k_new        = (const float*)d_in[1];
    const float* v_new        = (const float*)d_in[2];
    float*       key_cache    = (float*)d_in[3];   // written idempotently
    float*       value_cache  = (float*)d_in[4];
    const int*   block_list   = (const int*)d_in[5];
    const int*   block_groups = (const int*)d_in[6];
    // d_in[7] = block_mapping (one-hot of block_groups; unused — equivalent path via block_groups)
    const float* block_bias   = (const float*)d_in[8];
    const int*   block_indices= (const int*)d_in[9];
    const int*   block_offsets= (const int*)d_in[10];
    float* out = (float*)d_out;

    scatter_kv_kernel<<<PB, 256>>>(k_new, v_new, key_cache, value_cache,
                                   block_indices, block_offsets);

    dim3 g1(PNB, PKVH);
    attn_block_kernel<<<g1, 128>>>(query, key_cache, value_cache,
                                   block_list, block_groups, block_bias);

    dim3 g2(PB, PKVH);
    combine_kernel<<<g2, 128>>>(block_groups, out);
}